// round 15
// baseline (speedup 1.0000x reference)
#include <cuda_runtime.h>

// ---------------------------------------------------------------------------
// GCN layer (push-mode segment mean + tiny per-node MLPs)
// R14: persistent grid-stride edge kernel (grid = 152 SMs x 6 blocks) to
//      remove wave-quantization tail (~10.5 waves before). Everything else
//      is the measured-best R11/R13 configuration.
// ---------------------------------------------------------------------------

#define NODE_CAP 1048576  // N = 1e6 in this problem
#define EDGE_BLOCKS (152 * 6)  // GB300: 152 SMs, 6 CTAs/SM at 256 thr

// Scratch: xyz = neighbor-feature sum, w = degree
__device__ float4 g_accum[NODE_CAP];
// Repacked features: xyz = feature, w = 1.0 (one 16B sector-aligned gather)
__device__ float4 g_feat[NODE_CAP];

// ---------------- prep: zero accum + pack feature(+1.0), 1 node/thread -----
__global__ void prep_kernel(const float* __restrict__ feat, int n) {
    int i = blockIdx.x * blockDim.x + threadIdx.x;
    if (i < n) {
        g_accum[i] = make_float4(0.f, 0.f, 0.f, 0.f);
        g_feat[i]  = make_float4(feat[3 * i], feat[3 * i + 1], feat[3 * i + 2], 1.0f);
    }
}

// ---------------- edge phase (at LTS sector floor) ---------------------------
__device__ __forceinline__ void red_v4(int d, float4 f) {
    float4* p = g_accum + d;
    // volatile keeps the op; no "memory" clobber so gathers schedule freely.
    asm volatile("red.global.add.v4.f32 [%0], {%1, %2, %3, %4};"
                 :: "l"(p), "f"(f.x), "f"(f.y), "f"(f.z), "f"(f.w));
}

__global__ void __launch_bounds__(256, 6)
edge_kernel(const int* __restrict__ src,
            const int* __restrict__ dst,
            int e4, int rem) {
    const int stride = gridDim.x * blockDim.x;
    // persistent grid-stride loop over 4-edge packets
    for (int i = blockIdx.x * blockDim.x + threadIdx.x; i < e4; i += stride) {
        int4 s = reinterpret_cast<const int4*>(src)[i];
        int4 d = reinterpret_cast<const int4*>(dst)[i];
        // batch the 4 independent gathers first (MLP), then 4 reductions
        float4 f0 = __ldg(&g_feat[s.x]);
        float4 f1 = __ldg(&g_feat[s.y]);
        float4 f2 = __ldg(&g_feat[s.z]);
        float4 f3 = __ldg(&g_feat[s.w]);
        red_v4(d.x, f0);
        red_v4(d.y, f1);
        red_v4(d.z, f2);
        red_v4(d.w, f3);
    }
    // tail (E % 4 edges) handled by thread 0 of block 0
    if (rem && blockIdx.x == 0 && threadIdx.x == 0) {
        int base = e4 * 4;
        for (int k = 0; k < rem; k++)
            red_v4(dst[base + k], __ldg(&g_feat[src[base + k]]));
    }
}

// ---------------- node phase: 1 node/thread ---------------------------------
__global__ void node_kernel(const float* __restrict__ feat,
                            const float* __restrict__ x_attr,
                            const float* __restrict__ label,
                            const float* __restrict__ W0, const float* __restrict__ b0,
                            const float* __restrict__ W1, const float* __restrict__ b1,
                            const float* __restrict__ W2, const float* __restrict__ b2,
                            const float* __restrict__ Wa, const float* __restrict__ ba,
                            float* __restrict__ out, int n) {
    __shared__ float sW0[3], sW1[9], sW2[6], sWa[27], sB[3], sBa[3];
    int t = threadIdx.x;
    if (t < 3)  { sW0[t] = W0[t]; sB[t] = b0[t] + b1[t] + b2[t]; sBa[t] = ba[t]; }
    if (t < 9)  sW1[t] = W1[t];
    if (t < 6)  sW2[t] = W2[t];
    if (t < 27) sWa[t] = Wa[t];
    __syncthreads();

    int i = blockIdx.x * blockDim.x + threadIdx.x;
    if (i >= n) return;

    // batched independent loads
    float4 acc = g_accum[i];
    float f0 = feat[3 * i], f1 = feat[3 * i + 1], f2 = feat[3 * i + 2];
    float x0 = x_attr[2 * i], x1 = x_attr[2 * i + 1];
    float lb = label[i];

    float inv = 1.0f / fmaxf(acc.w, 1.0f);
    float hg0 = acc.x * inv, hg1 = acc.y * inv, hg2 = acc.z * inv;

    float a[3];
#pragma unroll
    for (int j = 0; j < 3; j++) {
        float v = lb * sW0[j]
                + hg0 * sW1[j] + hg1 * sW1[3 + j] + hg2 * sW1[6 + j]
                + x0 * sW2[j] + x1 * sW2[3 + j]
                + sB[j];
        a[j] = fmaxf(v, 0.f);
    }

#pragma unroll
    for (int j = 0; j < 3; j++) {
        float v = a[0] * sWa[j] + a[1] * sWa[3 + j] + a[2] * sWa[6 + j]
                + hg0 * sWa[9 + j] + hg1 * sWa[12 + j] + hg2 * sWa[15 + j]
                + f0 * sWa[18 + j] + f1 * sWa[21 + j] + f2 * sWa[24 + j]
                + sBa[j];
        out[3 * i + j] = fmaxf(v, 0.f);
    }
}

extern "C" void kernel_launch(void* const* d_in, const int* in_sizes, int n_in,
                              void* d_out, int out_size) {
    const float* feature = (const float*)d_in[0];
    const float* x_attr  = (const float*)d_in[1];
    const float* label   = (const float*)d_in[2];
    const float* W0 = (const float*)d_in[3];
    const float* b0 = (const float*)d_in[4];
    const float* W1 = (const float*)d_in[5];
    const float* b1 = (const float*)d_in[6];
    const float* W2 = (const float*)d_in[7];
    const float* b2 = (const float*)d_in[8];
    const float* Wa = (const float*)d_in[9];
    const float* ba = (const float*)d_in[10];
    const int*   src = (const int*)d_in[11];
    const int*   dst = (const int*)d_in[12];
    float* out = (float*)d_out;

    int N = in_sizes[0] / 3;
    int E = in_sizes[11];
    int e4 = E / 4;
    int rem = E % 4;

    const int TB = 256;
    prep_kernel<<<(N + TB - 1) / TB, TB>>>(feature, N);

    // persistent grid: exactly fills the chip; grid-stride covers all packets
    int edge_blocks = EDGE_BLOCKS;
    int max_blocks = (e4 + TB - 1) / TB;
    if (edge_blocks > max_blocks) edge_blocks = max_blocks > 0 ? max_blocks : 1;
    edge_kernel<<<edge_blocks, TB>>>(src, dst, e4, rem);

    node_kernel<<<(N + TB - 1) / TB, TB>>>(feature, x_attr, label,
                                           W0, b0, W1, b1, W2, b2, Wa, ba,
                                           out, N);
}

// round 16
// speedup vs baseline: 1.0117x; 1.0117x over previous
#include <cuda_runtime.h>

// ---------------------------------------------------------------------------
// GCN layer (push-mode segment mean + tiny per-node MLPs) — FINAL (R11 champ)
//
// Converged at the LTS roof: edge kernel measured L2=88.5% with the
// irreducible per-edge cost (1 random 16B gather sector + 1 REDG.v4 RMW).
//   prep ~8.8us (DRAM/L2 stream) | edge ~125.6us (LTS sector floor)
//   node ~14.5us (DRAM latency)  | total ~142us on a fast-clock hold
// ---------------------------------------------------------------------------

#define NODE_CAP 1048576  // N = 1e6 in this problem

// Scratch: xyz = neighbor-feature sum, w = degree
__device__ float4 g_accum[NODE_CAP];
// Repacked features: xyz = feature, w = 1.0 (one 16B sector-aligned gather;
// the w=1.0 lets the degree increment ride inside the same REDG.v4)
__device__ float4 g_feat[NODE_CAP];

// ---------------- prep: zero accum + pack feature(+1.0), 1 node/thread -----
__global__ void prep_kernel(const float* __restrict__ feat, int n) {
    int i = blockIdx.x * blockDim.x + threadIdx.x;
    if (i < n) {
        g_accum[i] = make_float4(0.f, 0.f, 0.f, 0.f);
        g_feat[i]  = make_float4(feat[3 * i], feat[3 * i + 1], feat[3 * i + 2], 1.0f);
    }
}

// ---------------- edge phase (at LTS sector floor) ---------------------------
__device__ __forceinline__ void red_v4(int d, float4 f) {
    float4* p = g_accum + d;
    // volatile keeps the op; no "memory" clobber so gathers schedule freely.
    asm volatile("red.global.add.v4.f32 [%0], {%1, %2, %3, %4};"
                 :: "l"(p), "f"(f.x), "f"(f.y), "f"(f.z), "f"(f.w));
}

__global__ void edge_kernel(const int* __restrict__ src,
                            const int* __restrict__ dst,
                            int e4, int rem) {
    int i = blockIdx.x * blockDim.x + threadIdx.x;
    if (i < e4) {
        int4 s = reinterpret_cast<const int4*>(src)[i];
        int4 d = reinterpret_cast<const int4*>(dst)[i];
        // batch the 4 independent gathers first (MLP), then 4 reductions
        float4 f0 = __ldg(&g_feat[s.x]);
        float4 f1 = __ldg(&g_feat[s.y]);
        float4 f2 = __ldg(&g_feat[s.z]);
        float4 f3 = __ldg(&g_feat[s.w]);
        red_v4(d.x, f0);
        red_v4(d.y, f1);
        red_v4(d.z, f2);
        red_v4(d.w, f3);
    } else if (i == e4 && rem) {
        int base = e4 * 4;
        for (int k = 0; k < rem; k++)
            red_v4(dst[base + k], __ldg(&g_feat[src[base + k]]));
    }
}

// ---------------- node phase: 1 node/thread ---------------------------------
__global__ void node_kernel(const float* __restrict__ feat,
                            const float* __restrict__ x_attr,
                            const float* __restrict__ label,
                            const float* __restrict__ W0, const float* __restrict__ b0,
                            const float* __restrict__ W1, const float* __restrict__ b1,
                            const float* __restrict__ W2, const float* __restrict__ b2,
                            const float* __restrict__ Wa, const float* __restrict__ ba,
                            float* __restrict__ out, int n) {
    __shared__ float sW0[3], sW1[9], sW2[6], sWa[27], sB[3], sBa[3];
    int t = threadIdx.x;
    if (t < 3)  { sW0[t] = W0[t]; sB[t] = b0[t] + b1[t] + b2[t]; sBa[t] = ba[t]; }
    if (t < 9)  sW1[t] = W1[t];
    if (t < 6)  sW2[t] = W2[t];
    if (t < 27) sWa[t] = Wa[t];
    __syncthreads();

    int i = blockIdx.x * blockDim.x + threadIdx.x;
    if (i >= n) return;

    // batched independent loads
    float4 acc = g_accum[i];
    float f0 = feat[3 * i], f1 = feat[3 * i + 1], f2 = feat[3 * i + 2];
    float x0 = x_attr[2 * i], x1 = x_attr[2 * i + 1];
    float lb = label[i];

    float inv = 1.0f / fmaxf(acc.w, 1.0f);
    float hg0 = acc.x * inv, hg1 = acc.y * inv, hg2 = acc.z * inv;

    float a[3];
#pragma unroll
    for (int j = 0; j < 3; j++) {
        float v = lb * sW0[j]
                + hg0 * sW1[j] + hg1 * sW1[3 + j] + hg2 * sW1[6 + j]
                + x0 * sW2[j] + x1 * sW2[3 + j]
                + sB[j];
        a[j] = fmaxf(v, 0.f);
    }

#pragma unroll
    for (int j = 0; j < 3; j++) {
        float v = a[0] * sWa[j] + a[1] * sWa[3 + j] + a[2] * sWa[6 + j]
                + hg0 * sWa[9 + j] + hg1 * sWa[12 + j] + hg2 * sWa[15 + j]
                + f0 * sWa[18 + j] + f1 * sWa[21 + j] + f2 * sWa[24 + j]
                + sBa[j];
        out[3 * i + j] = fmaxf(v, 0.f);
    }
}

extern "C" void kernel_launch(void* const* d_in, const int* in_sizes, int n_in,
                              void* d_out, int out_size) {
    const float* feature = (const float*)d_in[0];
    const float* x_attr  = (const float*)d_in[1];
    const float* label   = (const float*)d_in[2];
    const float* W0 = (const float*)d_in[3];
    const float* b0 = (const float*)d_in[4];
    const float* W1 = (const float*)d_in[5];
    const float* b1 = (const float*)d_in[6];
    const float* W2 = (const float*)d_in[7];
    const float* b2 = (const float*)d_in[8];
    const float* Wa = (const float*)d_in[9];
    const float* ba = (const float*)d_in[10];
    const int*   src = (const int*)d_in[11];
    const int*   dst = (const int*)d_in[12];
    float* out = (float*)d_out;

    int N = in_sizes[0] / 3;
    int E = in_sizes[11];
    int e4 = E / 4;
    int rem = E % 4;

    const int TB = 256;
    prep_kernel<<<(N + TB - 1) / TB, TB>>>(feature, N);

    int edge_thr = e4 + (rem ? 1 : 0);
    edge_kernel<<<(edge_thr + TB - 1) / TB, TB>>>(src, dst, e4, rem);

    node_kernel<<<(N + TB - 1) / TB, TB>>>(feature, x_attr, label,
                                           W0, b0, W1, b1, W2, b2, Wa, ba,
                                           out, N);
}

// round 17
// speedup vs baseline: 1.0120x; 1.0002x over previous
#include <cuda_runtime.h>

// ---------------------------------------------------------------------------
// GCN layer (push-mode segment mean + tiny per-node MLPs) — FINAL champion
//
// Converged at the LTS roof. Edge kernel profile (R10): L2=88.5%, DRAM=16.6%,
// issue=2.2% -> bound by random L2 sector transactions, ~89 B/edge:
//   32 B gather sector + ~64 B atomic RMW (sector read+write), irreducible
//   for a 16M-edge random segment-sum at N=1M on sm_103a.
// Breakdown (fast hold): prep ~8.5us | edge ~125.6us | node ~14.5us = ~142us.
//
// Measured-dead alternatives: evict_last policy (L2 thrash, +70us), split
// launches (+6us), vectorized prep/node (neutral-to-worse), __ldcg/__ldcs
// (neutral), launch_bounds & persistent grid (neutral), bf16 packing / CSR /
// sort / two-pass / smem privatization / TMA (costed dead: LTS is
// sector-granular and path-independent).
// ---------------------------------------------------------------------------

#define NODE_CAP 1048576  // N = 1e6 in this problem

// Scratch: xyz = neighbor-feature sum, w = degree
__device__ float4 g_accum[NODE_CAP];
// Repacked features: xyz = feature, w = 1.0 (one 16B sector-aligned gather;
// the w=1.0 lets the degree increment ride inside the same REDG.v4)
__device__ float4 g_feat[NODE_CAP];

// ---------------- prep: zero accum + pack feature(+1.0), 1 node/thread -----
__global__ void prep_kernel(const float* __restrict__ feat, int n) {
    int i = blockIdx.x * blockDim.x + threadIdx.x;
    if (i < n) {
        g_accum[i] = make_float4(0.f, 0.f, 0.f, 0.f);
        g_feat[i]  = make_float4(feat[3 * i], feat[3 * i + 1], feat[3 * i + 2], 1.0f);
    }
}

// ---------------- edge phase (at LTS sector floor) ---------------------------
__device__ __forceinline__ void red_v4(int d, float4 f) {
    float4* p = g_accum + d;
    // volatile keeps the op; no "memory" clobber so gathers schedule freely.
    asm volatile("red.global.add.v4.f32 [%0], {%1, %2, %3, %4};"
                 :: "l"(p), "f"(f.x), "f"(f.y), "f"(f.z), "f"(f.w));
}

__global__ void edge_kernel(const int* __restrict__ src,
                            const int* __restrict__ dst,
                            int e4, int rem) {
    int i = blockIdx.x * blockDim.x + threadIdx.x;
    if (i < e4) {
        int4 s = reinterpret_cast<const int4*>(src)[i];
        int4 d = reinterpret_cast<const int4*>(dst)[i];
        // batch the 4 independent gathers first (MLP), then 4 reductions
        float4 f0 = __ldg(&g_feat[s.x]);
        float4 f1 = __ldg(&g_feat[s.y]);
        float4 f2 = __ldg(&g_feat[s.z]);
        float4 f3 = __ldg(&g_feat[s.w]);
        red_v4(d.x, f0);
        red_v4(d.y, f1);
        red_v4(d.z, f2);
        red_v4(d.w, f3);
    } else if (i == e4 && rem) {
        int base = e4 * 4;
        for (int k = 0; k < rem; k++)
            red_v4(dst[base + k], __ldg(&g_feat[src[base + k]]));
    }
}

// ---------------- node phase: 1 node/thread ---------------------------------
__global__ void node_kernel(const float* __restrict__ feat,
                            const float* __restrict__ x_attr,
                            const float* __restrict__ label,
                            const float* __restrict__ W0, const float* __restrict__ b0,
                            const float* __restrict__ W1, const float* __restrict__ b1,
                            const float* __restrict__ W2, const float* __restrict__ b2,
                            const float* __restrict__ Wa, const float* __restrict__ ba,
                            float* __restrict__ out, int n) {
    __shared__ float sW0[3], sW1[9], sW2[6], sWa[27], sB[3], sBa[3];
    int t = threadIdx.x;
    if (t < 3)  { sW0[t] = W0[t]; sB[t] = b0[t] + b1[t] + b2[t]; sBa[t] = ba[t]; }
    if (t < 9)  sW1[t] = W1[t];
    if (t < 6)  sW2[t] = W2[t];
    if (t < 27) sWa[t] = Wa[t];
    __syncthreads();

    int i = blockIdx.x * blockDim.x + threadIdx.x;
    if (i >= n) return;

    // batched independent loads
    float4 acc = g_accum[i];
    float f0 = feat[3 * i], f1 = feat[3 * i + 1], f2 = feat[3 * i + 2];
    float x0 = x_attr[2 * i], x1 = x_attr[2 * i + 1];
    float lb = label[i];

    float inv = 1.0f / fmaxf(acc.w, 1.0f);
    float hg0 = acc.x * inv, hg1 = acc.y * inv, hg2 = acc.z * inv;

    float a[3];
#pragma unroll
    for (int j = 0; j < 3; j++) {
        float v = lb * sW0[j]
                + hg0 * sW1[j] + hg1 * sW1[3 + j] + hg2 * sW1[6 + j]
                + x0 * sW2[j] + x1 * sW2[3 + j]
                + sB[j];
        a[j] = fmaxf(v, 0.f);
    }

#pragma unroll
    for (int j = 0; j < 3; j++) {
        float v = a[0] * sWa[j] + a[1] * sWa[3 + j] + a[2] * sWa[6 + j]
                + hg0 * sWa[9 + j] + hg1 * sWa[12 + j] + hg2 * sWa[15 + j]
                + f0 * sWa[18 + j] + f1 * sWa[21 + j] + f2 * sWa[24 + j]
                + sBa[j];
        out[3 * i + j] = fmaxf(v, 0.f);
    }
}

extern "C" void kernel_launch(void* const* d_in, const int* in_sizes, int n_in,
                              void* d_out, int out_size) {
    const float* feature = (const float*)d_in[0];
    const float* x_attr  = (const float*)d_in[1];
    const float* label   = (const float*)d_in[2];
    const float* W0 = (const float*)d_in[3];
    const float* b0 = (const float*)d_in[4];
    const float* W1 = (const float*)d_in[5];
    const float* b1 = (const float*)d_in[6];
    const float* W2 = (const float*)d_in[7];
    const float* b2 = (const float*)d_in[8];
    const float* Wa = (const float*)d_in[9];
    const float* ba = (const float*)d_in[10];
    const int*   src = (const int*)d_in[11];
    const int*   dst = (const int*)d_in[12];
    float* out = (float*)d_out;

    int N = in_sizes[0] / 3;
    int E = in_sizes[11];
    int e4 = E / 4;
    int rem = E % 4;

    const int TB = 256;
    prep_kernel<<<(N + TB - 1) / TB, TB>>>(feature, N);

    int edge_thr = e4 + (rem ? 1 : 0);
    edge_kernel<<<(edge_thr + TB - 1) / TB, TB>>>(src, dst, e4, rem);

    node_kernel<<<(N + TB - 1) / TB, TB>>>(feature, x_attr, label,
                                           W0, b0, W1, b1, W2, b2, Wa, ba,
                                           out, N);
}